// round 2
// baseline (speedup 1.0000x reference)
#include <cuda_runtime.h>
#include <math.h>

#define BATCH 64
#define NF    1024
#define DIM   256
#define NEG   0.2f

// ---------------- scratch (device globals; no allocs allowed) ----------------
__device__ __align__(16) float g_q [BATCH*NF*DIM];
__device__ __align__(16) float g_k [BATCH*NF*DIM];
__device__ __align__(16) float g_v [BATCH*NF*DIM];
__device__ __align__(16) float g_ao[BATCH*NF*DIM];
__device__ __align__(16) float g_xc[BATCH*2*NF*DIM];
__device__ __align__(16) float g_wsum[DIM*NF];
__device__ __align__(16) float g_D [BATCH*DIM*DIM];
__device__ __align__(16) float g_Y [BATCH*NF*DIM];

// ---------------- gamma != 0 path (guarded; dead for bench inputs) ----------

// qkv[b,n,e] = sum_d x[b,n,d] * qkv_w[e,d] + qkv_b[e]
__global__ __launch_bounds__(256) void qkv_kernel(const float* __restrict__ x,
                                                  const float* __restrict__ w,
                                                  const float* __restrict__ bias,
                                                  const float* __restrict__ gamma) {
    if (gamma[0] == 0.0f) return;
    int row = blockIdx.x;                  // b*NF + n
    __shared__ float xs[DIM];
    xs[threadIdx.x] = x[(long)row*DIM + threadIdx.x];
    __syncthreads();
    for (int e = threadIdx.x; e < 3*DIM; e += 256) {
        float acc = bias[e];
        const float* wr = w + (long)e*DIM;
        #pragma unroll 4
        for (int d = 0; d < DIM; d++) acc += xs[d]*wr[d];
        float* dst = (e < DIM) ? g_q : (e < 2*DIM ? g_k : g_v);
        dst[(long)row*DIM + (e & (DIM-1))] = acc;
    }
}

// one block per (b,n): energy row -> softmax -> attn @ v row
__global__ __launch_bounds__(256) void attn_kernel(const float* __restrict__ gamma) {
    if (gamma[0] == 0.0f) return;
    int bn = blockIdx.x;
    int bb = bn / NF;
    __shared__ float qs[DIM];
    __shared__ float es[NF];
    __shared__ float red[256];
    int t = threadIdx.x;
    qs[t] = g_q[(long)bn*DIM + t];
    __syncthreads();
    const float* kbase = g_k + (long)bb*NF*DIM;
    for (int m = t; m < NF; m += 256) {
        float acc = 0.0f;
        const float* kr = kbase + (long)m*DIM;
        #pragma unroll 4
        for (int d = 0; d < DIM; d++) acc += qs[d]*kr[d];
        es[m] = acc;
    }
    __syncthreads();
    float mx = -INFINITY;
    for (int m = t; m < NF; m += 256) mx = fmaxf(mx, es[m]);
    red[t] = mx; __syncthreads();
    for (int s = 128; s > 0; s >>= 1) { if (t < s) red[t] = fmaxf(red[t], red[t+s]); __syncthreads(); }
    mx = red[0]; __syncthreads();
    float sm = 0.0f;
    for (int m = t; m < NF; m += 256) { float e = expf(es[m]-mx); es[m] = e; sm += e; }
    red[t] = sm; __syncthreads();
    for (int s = 128; s > 0; s >>= 1) { if (t < s) red[t] += red[t+s]; __syncthreads(); }
    float inv = 1.0f / red[0];
    __syncthreads();
    const float* vbase = g_v + (long)bb*NF*DIM;
    float acc = 0.0f;
    for (int m = 0; m < NF; m++) acc += es[m]*vbase[(long)m*DIM + t];
    g_ao[(long)bn*DIM + t] = acc * inv;
}

// xc = concat(gamma*out + x, x) along axis 1
__global__ void xc_kernel(const float* __restrict__ x, const float* __restrict__ gamma) {
    if (gamma[0] == 0.0f) return;
    float g = gamma[0];
    long i = (long)blockIdx.x*blockDim.x + threadIdx.x;   // < BATCH*2*NF*DIM
    long b = i / (2L*NF*DIM);
    long r = i % (2L*NF*DIM);
    long c = r / DIM, l = r % DIM;
    float val;
    if (c < NF) { long s = (b*NF + c)*DIM + l; val = g*g_ao[s] + x[s]; }
    else        { long s = (b*NF + (c-NF))*DIM + l; val = x[s]; }
    g_xc[i] = val;
}

// ---------------- gamma == 0 prep: Wsum = fc_w[:, :1024] + fc_w[:, 1024:] ----
__global__ void wsum_kernel(const float* __restrict__ fc_w, const float* __restrict__ gamma) {
    if (gamma[0] != 0.0f) return;
    int i = blockIdx.x*blockDim.x + threadIdx.x;   // < DIM*NF
    int o = i >> 10, c = i & (NF-1);
    g_wsum[i] = fc_w[(long)o*2*NF + c] + fc_w[(long)o*2*NF + NF + c];
}

// ---------------- tiled SGEMM: C = A(MxK,row) @ B(KxN,row), epilogues --------
// EPI: 0=none, 1=sigmoid(+bias[row]), 2=leaky, 3=bias[row]+leaky
template<int EPI>
__device__ __forceinline__ void sgemm_body(const float* __restrict__ A,
                                           const float* __restrict__ Bp,
                                           const float* __restrict__ bias,
                                           float* __restrict__ C,
                                           int N, int K) {
    __shared__ float As[16][64];
    __shared__ float Bs[16][64];

    int tid = threadIdx.x;
    int tx = tid & 15, ty = tid >> 4;
    int rowBase = blockIdx.y * 64;
    int colBase = blockIdx.x * 64;
    int aRow = tid >> 2, aCol = (tid & 3) << 2;
    int bRow = tid >> 4, bCol = (tid & 15) << 2;

    float acc[4][4] = {};
    for (int k0 = 0; k0 < K; k0 += 16) {
        float4 a4 = *reinterpret_cast<const float4*>(&A[(long)(rowBase + aRow)*K + k0 + aCol]);
        As[aCol+0][aRow] = a4.x;
        As[aCol+1][aRow] = a4.y;
        As[aCol+2][aRow] = a4.z;
        As[aCol+3][aRow] = a4.w;
        *reinterpret_cast<float4*>(&Bs[bRow][bCol]) =
            *reinterpret_cast<const float4*>(&Bp[(long)(k0 + bRow)*N + colBase + bCol]);
        __syncthreads();
        #pragma unroll
        for (int kk = 0; kk < 16; kk++) {
            float4 av = *reinterpret_cast<const float4*>(&As[kk][ty<<2]);
            float4 bv = *reinterpret_cast<const float4*>(&Bs[kk][tx<<2]);
            float a_[4] = {av.x, av.y, av.z, av.w};
            float b_[4] = {bv.x, bv.y, bv.z, bv.w};
            #pragma unroll
            for (int i = 0; i < 4; i++)
                #pragma unroll
                for (int j = 0; j < 4; j++)
                    acc[i][j] += a_[i]*b_[j];
        }
        __syncthreads();
    }
    #pragma unroll
    for (int i = 0; i < 4; i++) {
        int row = rowBase + (ty<<2) + i;
        float bv = (EPI == 1 || EPI == 3) ? bias[row] : 0.0f;
        float4 o;
        float v0 = acc[i][0] + bv, v1 = acc[i][1] + bv, v2 = acc[i][2] + bv, v3 = acc[i][3] + bv;
        if (EPI == 1) {
            v0 = 1.0f/(1.0f+expf(-v0)); v1 = 1.0f/(1.0f+expf(-v1));
            v2 = 1.0f/(1.0f+expf(-v2)); v3 = 1.0f/(1.0f+expf(-v3));
        }
        if (EPI == 2 || EPI == 3) {
            v0 = (v0 >= 0.f) ? v0 : NEG*v0; v1 = (v1 >= 0.f) ? v1 : NEG*v1;
            v2 = (v2 >= 0.f) ? v2 : NEG*v2; v3 = (v3 >= 0.f) ? v3 : NEG*v3;
        }
        o.x = v0; o.y = v1; o.z = v2; o.w = v3;
        *reinterpret_cast<float4*>(&C[(long)row*N + colBase + (tx<<2)]) = o;
    }
}

template<int EPI>
__global__ __launch_bounds__(256) void sgemm64(const float* __restrict__ Ag,
                                               const float* __restrict__ Bg,
                                               const float* __restrict__ bias,
                                               float* __restrict__ Cg,
                                               int N, int K,
                                               long sA, long sB, long sC) {
    sgemm_body<EPI>(Ag + (long)blockIdx.z*sA, Bg + (long)blockIdx.z*sB, bias,
                    Cg + (long)blockIdx.z*sC, N, K);
}

// GEMM A with in-kernel gamma dispatch:
//   gamma==0: D = sigmoid(Wsum @ x_b + fc_b)          (K=1024)
//   gamma!=0: D = sigmoid(fc_w @ xc_b + fc_b)         (K=2048)
__global__ __launch_bounds__(256) void gemmA_kernel(const float* __restrict__ gamma,
                                                    const float* __restrict__ fc_w,
                                                    const float* __restrict__ x,
                                                    const float* __restrict__ fc_b) {
    bool g0 = (gamma[0] == 0.0f);
    const float* A  = g0 ? g_wsum : fc_w;
    const float* Bp = g0 ? (x    + (long)blockIdx.z*NF*DIM)
                         : (g_xc + (long)blockIdx.z*2*NF*DIM);
    int K = g0 ? NF : 2*NF;
    float* C = g_D + (long)blockIdx.z*DIM*DIM;
    sgemm_body<1>(A, Bp, fc_b, C, DIM, K);
}

// ---------------- launch ----------------------------------------------------
extern "C" void kernel_launch(void* const* d_in, const int* in_sizes, int n_in,
                              void* d_out, int out_size) {
    // resolve inputs by element count (all distinct) for robustness
    const float *x = 0, *qkv_w = 0, *qkv_b = 0, *gamma = 0, *fc_w = 0, *fc_b = 0, *dw_w = 0, *dw_b = 0;
    for (int i = 0; i < n_in; i++) {
        switch (in_sizes[i]) {
            case BATCH*NF*DIM: x     = (const float*)d_in[i]; break;  // 16777216
            case 3*DIM*DIM:    qkv_w = (const float*)d_in[i]; break;  // 196608
            case 3*DIM:        qkv_b = (const float*)d_in[i]; break;  // 768
            case 1:            gamma = (const float*)d_in[i]; break;
            case DIM*2*NF:     fc_w  = (const float*)d_in[i]; break;  // 524288
            case DIM:          fc_b  = (const float*)d_in[i]; break;  // 256
            case NF*NF:        dw_w  = (const float*)d_in[i]; break;  // 1048576
            case NF:           dw_b  = (const float*)d_in[i]; break;  // 1024
        }
    }
    float* out = (float*)d_out;

    float *pD, *pY;
    cudaGetSymbolAddress((void**)&pD, g_D);
    cudaGetSymbolAddress((void**)&pY, g_Y);

    // attention path (device-side no-ops when gamma == 0)
    qkv_kernel <<<BATCH*NF, 256>>>(x, qkv_w, qkv_b, gamma);
    attn_kernel<<<BATCH*NF, 256>>>(gamma);
    xc_kernel  <<<(BATCH*2*NF*DIM)/256, 256>>>(x, gamma);

    // gamma==0 fold (device-side no-op when gamma != 0)
    wsum_kernel<<<(DIM*NF)/256, 256>>>(fc_w, gamma);

    // D = sigmoid(... + fc_b)           : per batch 256x256
    gemmA_kernel<<<dim3(DIM/64, DIM/64, BATCH), 256>>>(gamma, fc_w, x, fc_b);

    // Y = leaky(x_b @ D_b)              : per batch 1024x256, K=256
    sgemm64<2><<<dim3(DIM/64, NF/64, BATCH), 256>>>(
        x, pD, nullptr, pY, DIM, DIM,
        (long)NF*DIM, (long)DIM*DIM, (long)NF*DIM);

    // out = leaky(dw_w @ Y_b + dw_b)    : per batch 1024x256, K=1024
    sgemm64<3><<<dim3(DIM/64, NF/64, BATCH), 256>>>(
        dw_w, pY, dw_b, out, DIM, NF,
        0L, (long)NF*DIM, (long)NF*DIM);
}

// round 3
// speedup vs baseline: 1.2939x; 1.2939x over previous
#include <cuda_runtime.h>
#include <math.h>

#define BATCH 64
#define NF    1024
#define DIM   256
#define NEG   0.2f

// ---------------- scratch (device globals; no allocs allowed) ----------------
__device__ __align__(16) float g_q [BATCH*NF*DIM];
__device__ __align__(16) float g_k [BATCH*NF*DIM];
__device__ __align__(16) float g_v [BATCH*NF*DIM];
__device__ __align__(16) float g_ao[BATCH*NF*DIM];
__device__ __align__(16) float g_xc[BATCH*2*NF*DIM];
__device__ __align__(16) float g_wsum[DIM*NF];
__device__ __align__(16) float g_D [BATCH*DIM*DIM];
__device__ __align__(16) float g_Y [BATCH*NF*DIM];

// ---------------- gamma != 0 path (guarded; dead for bench inputs) ----------

__global__ __launch_bounds__(256) void qkv_kernel(const float* __restrict__ x,
                                                  const float* __restrict__ w,
                                                  const float* __restrict__ bias,
                                                  const float* __restrict__ gamma) {
    if (gamma[0] == 0.0f) return;
    __shared__ float xs[DIM];
    for (int row = blockIdx.x; row < BATCH*NF; row += gridDim.x) {
        xs[threadIdx.x] = x[(long)row*DIM + threadIdx.x];
        __syncthreads();
        for (int e = threadIdx.x; e < 3*DIM; e += 256) {
            float acc = bias[e];
            const float* wr = w + (long)e*DIM;
            #pragma unroll 4
            for (int d = 0; d < DIM; d++) acc += xs[d]*wr[d];
            float* dst = (e < DIM) ? g_q : (e < 2*DIM ? g_k : g_v);
            dst[(long)row*DIM + (e & (DIM-1))] = acc;
        }
        __syncthreads();
    }
}

__global__ __launch_bounds__(256) void attn_kernel(const float* __restrict__ gamma) {
    if (gamma[0] == 0.0f) return;
    __shared__ float qs[DIM];
    __shared__ float es[NF];
    __shared__ float red[256];
    int t = threadIdx.x;
    for (int bn = blockIdx.x; bn < BATCH*NF; bn += gridDim.x) {
        int bb = bn / NF;
        qs[t] = g_q[(long)bn*DIM + t];
        __syncthreads();
        const float* kbase = g_k + (long)bb*NF*DIM;
        for (int m = t; m < NF; m += 256) {
            float acc = 0.0f;
            const float* kr = kbase + (long)m*DIM;
            #pragma unroll 4
            for (int d = 0; d < DIM; d++) acc += qs[d]*kr[d];
            es[m] = acc;
        }
        __syncthreads();
        float mx = -INFINITY;
        for (int m = t; m < NF; m += 256) mx = fmaxf(mx, es[m]);
        red[t] = mx; __syncthreads();
        for (int s = 128; s > 0; s >>= 1) { if (t < s) red[t] = fmaxf(red[t], red[t+s]); __syncthreads(); }
        mx = red[0]; __syncthreads();
        float sm = 0.0f;
        for (int m = t; m < NF; m += 256) { float e = expf(es[m]-mx); es[m] = e; sm += e; }
        red[t] = sm; __syncthreads();
        for (int s = 128; s > 0; s >>= 1) { if (t < s) red[t] += red[t+s]; __syncthreads(); }
        float inv = 1.0f / red[0];
        __syncthreads();
        const float* vbase = g_v + (long)bb*NF*DIM;
        float acc = 0.0f;
        for (int m = 0; m < NF; m++) acc += es[m]*vbase[(long)m*DIM + t];
        g_ao[(long)bn*DIM + t] = acc * inv;
        __syncthreads();
    }
}

// prep: mutually exclusive paths.
//   gamma==0: g_wsum = fc_w[:, :NF] + fc_w[:, NF:]
//   gamma!=0: g_xc = concat(gamma*attn_out + x, x)
__global__ __launch_bounds__(256) void prep_kernel(const float* __restrict__ x,
                                                   const float* __restrict__ fc_w,
                                                   const float* __restrict__ gamma) {
    float g = gamma[0];
    if (g == 0.0f) {
        for (long i = (long)blockIdx.x*256 + threadIdx.x; i < (long)DIM*NF; i += (long)gridDim.x*256) {
            long o = i >> 10, c = i & (NF-1);
            g_wsum[i] = fc_w[o*2*NF + c] + fc_w[o*2*NF + NF + c];
        }
    } else {
        for (long i = (long)blockIdx.x*256 + threadIdx.x; i < (long)BATCH*2*NF*DIM; i += (long)gridDim.x*256) {
            long b = i / (2L*NF*DIM);
            long r = i % (2L*NF*DIM);
            long c = r / DIM, l = r % DIM;
            float val;
            if (c < NF) { long s = (b*NF + c)*DIM + l; val = g*g_ao[s] + x[s]; }
            else        { long s = (b*NF + (c-NF))*DIM + l; val = x[s]; }
            g_xc[i] = val;
        }
    }
}

// ---------------- f32x2 tiled SGEMM: C = A(MxK,row) @ B(KxN,row) -------------
// Tile 128x128, K-tile 16, 256 threads, 8x8 microtile, packed fma.rn.f32x2.
// EPI: 1=sigmoid(+bias[row]), 2=leaky, 3=bias[row]+leaky
#define TM 128
#define TN 128
#define TK 16

__device__ __forceinline__ unsigned long long splat2(float a) {
    unsigned long long r;
    unsigned int u = __float_as_uint(a);
    asm("mov.b64 %0, {%1, %1};" : "=l"(r) : "r"(u));
    return r;
}
__device__ __forceinline__ void fma2(unsigned long long& d, unsigned long long a, unsigned long long b) {
    asm("fma.rn.f32x2 %0, %1, %2, %0;" : "+l"(d) : "l"(a), "l"(b));
}
__device__ __forceinline__ float2 unpack2(unsigned long long v) {
    unsigned int lo, hi;
    asm("mov.b64 {%0, %1}, %2;" : "=r"(lo), "=r"(hi) : "l"(v));
    return make_float2(__uint_as_float(lo), __uint_as_float(hi));
}

template<int EPI>
__device__ __forceinline__ void sgemm_body(const float* __restrict__ A,
                                           const float* __restrict__ Bp,
                                           const float* __restrict__ bias,
                                           float* __restrict__ C,
                                           int N, int K) {
    __shared__ float As[TK][TM];
    __shared__ float Bs[TK][TN];

    int tid = threadIdx.x;
    int tx = tid & 15, ty = tid >> 4;           // 16x16 threads, 8x8 microtile
    int rowBase = blockIdx.y * TM;
    int colBase = blockIdx.x * TN;
    int ar = tid >> 1, ac = (tid & 1) << 3;     // A: 128 rows x 16 cols, 8 floats/thread
    int bk = tid >> 4, bn = (tid & 15) << 3;    // B: 16 rows x 128 cols, 8 floats/thread

    unsigned long long acc2[8][4];
    #pragma unroll
    for (int i = 0; i < 8; i++)
        #pragma unroll
        for (int j = 0; j < 4; j++) acc2[i][j] = 0ull;

    for (int k0 = 0; k0 < K; k0 += TK) {
        float4 a0 = *reinterpret_cast<const float4*>(&A[(long)(rowBase + ar)*K + k0 + ac]);
        float4 a1 = *reinterpret_cast<const float4*>(&A[(long)(rowBase + ar)*K + k0 + ac + 4]);
        float4 b0 = *reinterpret_cast<const float4*>(&Bp[(long)(k0 + bk)*N + colBase + bn]);
        float4 b1 = *reinterpret_cast<const float4*>(&Bp[(long)(k0 + bk)*N + colBase + bn + 4]);
        As[ac+0][ar] = a0.x; As[ac+1][ar] = a0.y; As[ac+2][ar] = a0.z; As[ac+3][ar] = a0.w;
        As[ac+4][ar] = a1.x; As[ac+5][ar] = a1.y; As[ac+6][ar] = a1.z; As[ac+7][ar] = a1.w;
        *reinterpret_cast<float4*>(&Bs[bk][bn])     = b0;
        *reinterpret_cast<float4*>(&Bs[bk][bn + 4]) = b1;
        __syncthreads();
        #pragma unroll
        for (int kk = 0; kk < TK; kk++) {
            float4 af0 = *reinterpret_cast<const float4*>(&As[kk][ty << 3]);
            float4 af1 = *reinterpret_cast<const float4*>(&As[kk][(ty << 3) + 4]);
            const unsigned long long* bpp =
                reinterpret_cast<const unsigned long long*>(&Bs[kk][tx << 3]);
            unsigned long long bb0 = bpp[0], bb1 = bpp[1], bb2 = bpp[2], bb3 = bpp[3];
            float av[8] = {af0.x, af0.y, af0.z, af0.w, af1.x, af1.y, af1.z, af1.w};
            #pragma unroll
            for (int i = 0; i < 8; i++) {
                unsigned long long aa = splat2(av[i]);
                fma2(acc2[i][0], aa, bb0);
                fma2(acc2[i][1], aa, bb1);
                fma2(acc2[i][2], aa, bb2);
                fma2(acc2[i][3], aa, bb3);
            }
        }
        __syncthreads();
    }

    #pragma unroll
    for (int i = 0; i < 8; i++) {
        int row = rowBase + (ty << 3) + i;
        float bv = (EPI == 1 || EPI == 3) ? bias[row] : 0.0f;
        float v[8];
        #pragma unroll
        for (int j = 0; j < 4; j++) {
            float2 p = unpack2(acc2[i][j]);
            v[2*j] = p.x + bv; v[2*j+1] = p.y + bv;
        }
        #pragma unroll
        for (int j = 0; j < 8; j++) {
            if (EPI == 1) v[j] = 1.0f/(1.0f + expf(-v[j]));
            if (EPI == 2 || EPI == 3) v[j] = (v[j] >= 0.f) ? v[j] : NEG*v[j];
        }
        float4 o0 = make_float4(v[0], v[1], v[2], v[3]);
        float4 o1 = make_float4(v[4], v[5], v[6], v[7]);
        *reinterpret_cast<float4*>(&C[(long)row*N + colBase + (tx << 3)])     = o0;
        *reinterpret_cast<float4*>(&C[(long)row*N + colBase + (tx << 3) + 4]) = o1;
    }
}

template<int EPI>
__global__ __launch_bounds__(256, 2) void sgemm128(const float* __restrict__ Ag,
                                                   const float* __restrict__ Bg,
                                                   const float* __restrict__ bias,
                                                   float* __restrict__ Cg,
                                                   int N, int K,
                                                   long sA, long sB, long sC) {
    sgemm_body<EPI>(Ag + (long)blockIdx.z*sA, Bg + (long)blockIdx.z*sB, bias,
                    Cg + (long)blockIdx.z*sC, N, K);
}

// GEMM A with in-kernel gamma dispatch:
//   gamma==0: D = sigmoid(Wsum @ x_b + fc_b)    (K=1024)
//   gamma!=0: D = sigmoid(fc_w @ xc_b + fc_b)   (K=2048)
__global__ __launch_bounds__(256, 2) void gemmA_kernel(const float* __restrict__ gamma,
                                                       const float* __restrict__ fc_w,
                                                       const float* __restrict__ x,
                                                       const float* __restrict__ fc_b) {
    bool g0 = (gamma[0] == 0.0f);
    const float* A  = g0 ? g_wsum : fc_w;
    const float* Bp = g0 ? (x    + (long)blockIdx.z*NF*DIM)
                         : (g_xc + (long)blockIdx.z*2*NF*DIM);
    int K = g0 ? NF : 2*NF;
    float* C = g_D + (long)blockIdx.z*DIM*DIM;
    sgemm_body<1>(A, Bp, fc_b, C, DIM, K);
}

// ---------------- launch ----------------------------------------------------
extern "C" void kernel_launch(void* const* d_in, const int* in_sizes, int n_in,
                              void* d_out, int out_size) {
    const float *x = 0, *qkv_w = 0, *qkv_b = 0, *gamma = 0, *fc_w = 0, *fc_b = 0, *dw_w = 0, *dw_b = 0;
    for (int i = 0; i < n_in; i++) {
        switch (in_sizes[i]) {
            case BATCH*NF*DIM: x     = (const float*)d_in[i]; break;
            case 3*DIM*DIM:    qkv_w = (const float*)d_in[i]; break;
            case 3*DIM:        qkv_b = (const float*)d_in[i]; break;
            case 1:            gamma = (const float*)d_in[i]; break;
            case DIM*2*NF:     fc_w  = (const float*)d_in[i]; break;
            case DIM:          fc_b  = (const float*)d_in[i]; break;
            case NF*NF:        dw_w  = (const float*)d_in[i]; break;
            case NF:           dw_b  = (const float*)d_in[i]; break;
        }
    }
    float* out = (float*)d_out;

    float *pD, *pY;
    cudaGetSymbolAddress((void**)&pD, g_D);
    cudaGetSymbolAddress((void**)&pY, g_Y);

    // 1,2: attention path (grid-stride; near-instant no-ops when gamma == 0)
    qkv_kernel <<<1184, 256>>>(x, qkv_w, qkv_b, gamma);
    attn_kernel<<<1184, 256>>>(gamma);

    // 3: prep (wsum when gamma==0, xc when gamma!=0)
    prep_kernel<<<1024, 256>>>(x, fc_w, gamma);

    // 4: D = sigmoid(... + fc_b)         per batch 256x256
    gemmA_kernel<<<dim3(DIM/TN, DIM/TM, BATCH), 256>>>(gamma, fc_w, x, fc_b);

    // 5: Y = leaky(x_b @ D_b)            per batch 1024x256, K=256
    sgemm128<2><<<dim3(DIM/TN, NF/TM, BATCH), 256>>>(
        x, pD, nullptr, pY, DIM, DIM,
        (long)NF*DIM, (long)DIM*DIM, (long)NF*DIM);

    // 6: out = leaky(dw_w @ Y_b + dw_b)  per batch 1024x256, K=1024  (ncu -s 5 target)
    sgemm128<3><<<dim3(DIM/TN, NF/TM, BATCH), 256>>>(
        dw_w, pY, dw_b, out, DIM, NF,
        0L, (long)NF*DIM, (long)NF*DIM);
}

// round 5
// speedup vs baseline: 2.4454x; 1.8900x over previous
#include <cuda_runtime.h>
#include <cuda_bf16.h>
#include <math.h>
#include <stdint.h>

#define BATCH 64
#define NF    1024
#define DIM   256
#define NEG   0.2f

// ================= device scratch (no allocs allowed) ========================
// gamma != 0 fallback path (fp32)
__device__ __align__(16) float g_q [BATCH*NF*DIM];
__device__ __align__(16) float g_k [BATCH*NF*DIM];
__device__ __align__(16) float g_v [BATCH*NF*DIM];
__device__ __align__(16) float g_ao[BATCH*NF*DIM];
__device__ __align__(16) float g_xc[BATCH*2*NF*DIM];
__device__ __align__(16) float g_D [BATCH*DIM*DIM];
__device__ __align__(16) float g_Y [BATCH*NF*DIM];
// gamma == 0 tensor path (bf16 hi/lo splits)
__device__ __align__(16) __nv_bfloat16 g_ws_hi[DIM*NF],        g_ws_lo[DIM*NF];
__device__ __align__(16) __nv_bfloat16 g_x_hi [BATCH*NF*DIM],  g_x_lo [BATCH*NF*DIM];
__device__ __align__(16) __nv_bfloat16 g_xT_hi[BATCH*DIM*NF],  g_xT_lo[BATCH*DIM*NF];
__device__ __align__(16) __nv_bfloat16 g_dw_hi[NF*NF],         g_dw_lo[NF*NF];
__device__ __align__(16) __nv_bfloat16 g_DT_hi[BATCH*DIM*DIM], g_DT_lo[BATCH*DIM*DIM];
__device__ __align__(16) __nv_bfloat16 g_YT_hi[BATCH*DIM*NF],  g_YT_lo[BATCH*DIM*NF];

// ================= PTX helpers (family-safe: sm_80-era only) =================
__device__ __forceinline__ uint32_t s2u(const void* p) {
    uint32_t a;
    asm("{ .reg .u64 t; cvta.to.shared.u64 t, %1; cvt.u32.u64 %0, t; }" : "=r"(a) : "l"(p));
    return a;
}
__device__ __forceinline__ void cp16(uint32_t dst, const void* src) {
    asm volatile("cp.async.ca.shared.global [%0], [%1], 16;" :: "r"(dst), "l"(src));
}
#define CP_COMMIT() asm volatile("cp.async.commit_group;" ::: "memory")
#define CP_WAIT1()  asm volatile("cp.async.wait_group 1;"  ::: "memory")

__device__ __forceinline__ void ldm_x4(uint32_t& r0, uint32_t& r1, uint32_t& r2, uint32_t& r3,
                                       uint32_t addr) {
    asm volatile("ldmatrix.sync.aligned.m8n8.x4.shared.b16 {%0,%1,%2,%3}, [%4];"
                 : "=r"(r0), "=r"(r1), "=r"(r2), "=r"(r3) : "r"(addr));
}
__device__ __forceinline__ void mma_bf16(float* c, const uint32_t* a, const uint32_t* b) {
    asm volatile("mma.sync.aligned.m16n8k16.row.col.f32.bf16.bf16.f32 "
                 "{%0,%1,%2,%3}, {%4,%5,%6,%7}, {%8,%9}, {%0,%1,%2,%3};"
                 : "+f"(c[0]), "+f"(c[1]), "+f"(c[2]), "+f"(c[3])
                 : "r"(a[0]), "r"(a[1]), "r"(a[2]), "r"(a[3]), "r"(b[0]), "r"(b[1]));
}
__device__ __forceinline__ uint32_t pack_bf16(__nv_bfloat16 a, __nv_bfloat16 b) {
    return (uint32_t)__bfloat16_as_ushort(a) | ((uint32_t)__bfloat16_as_ushort(b) << 16);
}

// ================= HMMA GEMM: C[M,N] = A[M,K] @ B[N,K]^T  (both K-major) =====
// 3-term bf16 split accumulate: Ahi*Bhi + Ahi*Blo + Alo*Bhi, fp32 accum.
// CTA tile 128x128, K-tile 32, 8 warps (4x2), warp tile 32x64.
// smem row pitch 40 bf16 (80B) -> conflict-free ldmatrix, no swizzle.
// EPI 1: sigmoid(acc + bias[col]) -> bf16 hi/lo row-major out
// EPI 2: leaky(acc)               -> bf16 hi/lo row-major out
// EPI 3: leaky(acc + bias[row])   -> fp32 row-major out
#define ST    3
#define BK    32
#define PITCH 40
#define STAGE_BYTES 20480   // (128*40)*2 bytes per tile, A + B

template<int EPI>
__device__ void tgemm_body(const __nv_bfloat16* __restrict__ Ahi,
                           const __nv_bfloat16* __restrict__ Alo,
                           const __nv_bfloat16* __restrict__ Bhi,
                           const __nv_bfloat16* __restrict__ Blo,
                           int K, const float* __restrict__ bias,
                           __nv_bfloat16* __restrict__ outHi,
                           __nv_bfloat16* __restrict__ outLo,
                           float* __restrict__ outF, int ldOut) {
    extern __shared__ char smc[];
    uint32_t sbase = s2u(smc);
    int tid = threadIdx.x, lane = tid & 31, wid = tid >> 5;
    int mBase = blockIdx.y * 128, nBase = blockIdx.x * 128;
    int wRow = (wid >> 1) * 32, wCol = (wid & 1) * 64;

    const __nv_bfloat16* segA[3] = {Ahi, Ahi, Alo};
    const __nv_bfloat16* segB[3] = {Bhi, Blo, Bhi};
    int segN = K / BK, total = 3 * segN;

    auto load_stage = [&](int s, int kk) {
        int sg = kk / segN, k0 = (kk - sg * segN) * BK;
        const __nv_bfloat16* A = segA[sg];
        const __nv_bfloat16* B = segB[sg];
        uint32_t aoff = sbase + s * STAGE_BYTES;
        uint32_t boff = aoff + 10240;
        #pragma unroll
        for (int q = 0; q < 2; q++) {
            int ch = tid * 2 + q;            // 0..511
            int row = ch >> 2, c16 = ch & 3;
            uint32_t d = (uint32_t)(row * PITCH + c16 * 8) * 2;
            cp16(aoff + d, A + (size_t)(mBase + row) * K + k0 + c16 * 8);
            cp16(boff + d, B + (size_t)(nBase + row) * K + k0 + c16 * 8);
        }
        CP_COMMIT();
    };

    load_stage(0, 0);
    load_stage(1, 1);

    float acc[2][8][4];
    #pragma unroll
    for (int i = 0; i < 2; i++)
        #pragma unroll
        for (int j = 0; j < 8; j++)
            #pragma unroll
            for (int q = 0; q < 4; q++) acc[i][j][q] = 0.0f;

    for (int kk = 0; kk < total; kk++) {
        int s = kk % ST;
        CP_WAIT1();
        __syncthreads();
        if (kk + 2 < total) load_stage((kk + 2) % ST, kk + 2);
        uint32_t aT = sbase + s * STAGE_BYTES;
        uint32_t bT = aT + 10240;
        #pragma unroll
        for (int kf = 0; kf < 2; kf++) {
            uint32_t a[2][4];
            #pragma unroll
            for (int i = 0; i < 2; i++) {
                int r = wRow + i * 16 + (lane & 15);
                int c = kf * 16 + ((lane & 16) ? 8 : 0);
                ldm_x4(a[i][0], a[i][1], a[i][2], a[i][3], aT + (uint32_t)(r * PITCH + c) * 2);
            }
            uint32_t b[8][2];
            #pragma unroll
            for (int nf2 = 0; nf2 < 4; nf2++) {
                int n = wCol + nf2 * 16 + (lane & 7) + ((lane & 16) ? 8 : 0);
                int c = kf * 16 + ((lane & 8) ? 8 : 0);
                uint32_t r0, r1, r2, r3;
                ldm_x4(r0, r1, r2, r3, bT + (uint32_t)(n * PITCH + c) * 2);
                b[nf2*2][0] = r0; b[nf2*2][1] = r1;
                b[nf2*2+1][0] = r2; b[nf2*2+1][1] = r3;
            }
            #pragma unroll
            for (int i = 0; i < 2; i++)
                #pragma unroll
                for (int j = 0; j < 8; j++)
                    mma_bf16(acc[i][j], a[i], b[j]);
        }
    }

    // ---- epilogue (no transpose needed anywhere) ----
    int r0 = mBase + wRow + (lane >> 2);
    int c0 = nBase + wCol + (lane & 3) * 2;
    #pragma unroll
    for (int i = 0; i < 2; i++) {
        #pragma unroll
        for (int h = 0; h < 2; h++) {
            int row = r0 + i * 16 + h * 8;
            float rbv = (EPI == 3) ? bias[row] : 0.0f;
            #pragma unroll
            for (int j = 0; j < 8; j++) {
                float v0 = acc[i][j][h*2+0];
                float v1 = acc[i][j][h*2+1];
                int col = c0 + j * 8;
                if (EPI == 1) {
                    v0 += bias[col]; v1 += bias[col + 1];
                    v0 = 1.0f / (1.0f + expf(-v0));
                    v1 = 1.0f / (1.0f + expf(-v1));
                } else if (EPI == 2) {
                    v0 = (v0 >= 0.f) ? v0 : NEG * v0;
                    v1 = (v1 >= 0.f) ? v1 : NEG * v1;
                } else {
                    v0 += rbv; v1 += rbv;
                    v0 = (v0 >= 0.f) ? v0 : NEG * v0;
                    v1 = (v1 >= 0.f) ? v1 : NEG * v1;
                }
                if (EPI == 3) {
                    *reinterpret_cast<float2*>(outF + (size_t)row * ldOut + col) =
                        make_float2(v0, v1);
                } else {
                    __nv_bfloat16 h0 = __float2bfloat16_rn(v0);
                    __nv_bfloat16 h1 = __float2bfloat16_rn(v1);
                    __nv_bfloat16 l0 = __float2bfloat16_rn(v0 - __bfloat162float(h0));
                    __nv_bfloat16 l1 = __float2bfloat16_rn(v1 - __bfloat162float(h1));
                    size_t off = (size_t)row * ldOut + col;
                    *reinterpret_cast<uint32_t*>(outHi + off) = pack_bf16(h0, h1);
                    *reinterpret_cast<uint32_t*>(outLo + off) = pack_bf16(l0, l1);
                }
            }
        }
    }
}

// DT[l,o] = sigmoid( xT_b[l,:] . Wsum[o,:] + fc_b[o] )      M=256,N=256,K=1024
__global__ __launch_bounds__(256, 2)
void tgA(const float* __restrict__ gamma, const float* __restrict__ fc_b) {
    if (gamma[0] != 0.0f) return;
    size_t b = blockIdx.z;
    tgemm_body<1>(g_xT_hi + b * DIM * NF, g_xT_lo + b * DIM * NF,
                  g_ws_hi, g_ws_lo, NF, fc_b,
                  g_DT_hi + b * DIM * DIM, g_DT_lo + b * DIM * DIM, nullptr, DIM);
}
// YT[l,n] = leaky( DT_b[l,:] . x_b[n,:] )                    M=256,N=1024,K=256
__global__ __launch_bounds__(256, 2)
void tgB(const float* __restrict__ gamma) {
    if (gamma[0] != 0.0f) return;
    size_t b = blockIdx.z;
    tgemm_body<2>(g_DT_hi + b * DIM * DIM, g_DT_lo + b * DIM * DIM,
                  g_x_hi + b * NF * DIM, g_x_lo + b * NF * DIM, DIM, nullptr,
                  g_YT_hi + b * DIM * NF, g_YT_lo + b * DIM * NF, nullptr, NF);
}
// out[o,l] = leaky( dw[o,:] . YT_b[l,:] + dw_b[o] )          M=1024,N=256,K=1024
__global__ __launch_bounds__(256, 2)
void tgC(const float* __restrict__ gamma, const float* __restrict__ dw_b,
         float* __restrict__ out) {
    if (gamma[0] != 0.0f) return;
    size_t b = blockIdx.z;
    tgemm_body<3>(g_dw_hi, g_dw_lo,
                  g_YT_hi + b * DIM * NF, g_YT_lo + b * DIM * NF, NF, dw_b,
                  nullptr, nullptr, out + b * NF * DIM, DIM);
}

// ================= conversion kernels (gamma == 0) ===========================
__global__ void conv_wsum(const float* __restrict__ fc_w, const float* __restrict__ gamma) {
    if (gamma[0] != 0.0f) return;
    int i = blockIdx.x * 256 + threadIdx.x;           // < DIM*NF
    int o = i >> 10, c = i & 1023;
    float w = fc_w[(size_t)o * 2048 + c] + fc_w[(size_t)o * 2048 + 1024 + c];
    __nv_bfloat16 h = __float2bfloat16_rn(w);
    g_ws_hi[i] = h;
    g_ws_lo[i] = __float2bfloat16_rn(w - __bfloat162float(h));
}
// x -> straight split (g_x) AND transposed split (g_xT) in one pass
__global__ void conv_x(const float* __restrict__ x, const float* __restrict__ gamma) {
    if (gamma[0] != 0.0f) return;
    __shared__ float t[32][33];
    int n0 = blockIdx.x * 32, d0 = blockIdx.y * 32, b = blockIdx.z;
    int tx = threadIdx.x, ty = threadIdx.y;
    const float* xb = x + (size_t)b * NF * DIM;
    #pragma unroll
    for (int i = 0; i < 4; i++) {
        int n = n0 + ty + 8 * i;
        float v = xb[(size_t)n * DIM + d0 + tx];
        t[ty + 8 * i][tx] = v;
        __nv_bfloat16 h = __float2bfloat16_rn(v);
        size_t o = (size_t)b * NF * DIM + (size_t)n * DIM + d0 + tx;
        g_x_hi[o] = h;
        g_x_lo[o] = __float2bfloat16_rn(v - __bfloat162float(h));
    }
    __syncthreads();
    #pragma unroll
    for (int i = 0; i < 4; i++) {
        int d = d0 + ty + 8 * i, n = n0 + tx;
        float v = t[tx][ty + 8 * i];
        __nv_bfloat16 h = __float2bfloat16_rn(v);
        size_t o = (size_t)b * DIM * NF + (size_t)d * NF + n;
        g_xT_hi[o] = h;
        g_xT_lo[o] = __float2bfloat16_rn(v - __bfloat162float(h));
    }
}
__global__ void conv_split4(const float* __restrict__ src, const float* __restrict__ gamma,
                            __nv_bfloat16* __restrict__ hi, __nv_bfloat16* __restrict__ lo) {
    if (gamma[0] != 0.0f) return;
    size_t i = ((size_t)blockIdx.x * 256 + threadIdx.x) * 4;
    float4 v = *reinterpret_cast<const float4*>(src + i);
    __nv_bfloat16 h0 = __float2bfloat16_rn(v.x), h1 = __float2bfloat16_rn(v.y);
    __nv_bfloat16 h2 = __float2bfloat16_rn(v.z), h3 = __float2bfloat16_rn(v.w);
    uint2 ho, lw;
    ho.x = pack_bf16(h0, h1); ho.y = pack_bf16(h2, h3);
    lw.x = pack_bf16(__float2bfloat16_rn(v.x - __bfloat162float(h0)),
                     __float2bfloat16_rn(v.y - __bfloat162float(h1)));
    lw.y = pack_bf16(__float2bfloat16_rn(v.z - __bfloat162float(h2)),
                     __float2bfloat16_rn(v.w - __bfloat162float(h3)));
    *reinterpret_cast<uint2*>(hi + i) = ho;
    *reinterpret_cast<uint2*>(lo + i) = lw;
}

// ================= gamma != 0 fallback (SIMT f32x2 path) =====================
__global__ __launch_bounds__(256) void qkv_kernel(const float* __restrict__ x,
                                                  const float* __restrict__ w,
                                                  const float* __restrict__ bias,
                                                  const float* __restrict__ gamma) {
    if (gamma[0] == 0.0f) return;
    __shared__ float xs[DIM];
    for (int row = blockIdx.x; row < BATCH*NF; row += gridDim.x) {
        xs[threadIdx.x] = x[(long)row*DIM + threadIdx.x];
        __syncthreads();
        for (int e = threadIdx.x; e < 3*DIM; e += 256) {
            float acc = bias[e];
            const float* wr = w + (long)e*DIM;
            #pragma unroll 4
            for (int d = 0; d < DIM; d++) acc += xs[d]*wr[d];
            float* dst = (e < DIM) ? g_q : (e < 2*DIM ? g_k : g_v);
            dst[(long)row*DIM + (e & (DIM-1))] = acc;
        }
        __syncthreads();
    }
}
__global__ __launch_bounds__(256) void attn_kernel(const float* __restrict__ gamma) {
    if (gamma[0] == 0.0f) return;
    __shared__ float qs[DIM];
    __shared__ float es[NF];
    __shared__ float red[256];
    int t = threadIdx.x;
    for (int bn = blockIdx.x; bn < BATCH*NF; bn += gridDim.x) {
        int bb = bn / NF;
        qs[t] = g_q[(long)bn*DIM + t];
        __syncthreads();
        const float* kbase = g_k + (long)bb*NF*DIM;
        for (int m = t; m < NF; m += 256) {
            float acc = 0.0f;
            const float* kr = kbase + (long)m*DIM;
            #pragma unroll 4
            for (int d = 0; d < DIM; d++) acc += qs[d]*kr[d];
            es[m] = acc;
        }
        __syncthreads();
        float mx = -INFINITY;
        for (int m = t; m < NF; m += 256) mx = fmaxf(mx, es[m]);
        red[t] = mx; __syncthreads();
        for (int s = 128; s > 0; s >>= 1) { if (t < s) red[t] = fmaxf(red[t], red[t+s]); __syncthreads(); }
        mx = red[0]; __syncthreads();
        float sm = 0.0f;
        for (int m = t; m < NF; m += 256) { float e = expf(es[m]-mx); es[m] = e; sm += e; }
        red[t] = sm; __syncthreads();
        for (int s = 128; s > 0; s >>= 1) { if (t < s) red[t] += red[t+s]; __syncthreads(); }
        float inv = 1.0f / red[0];
        __syncthreads();
        const float* vbase = g_v + (long)bb*NF*DIM;
        float acc = 0.0f;
        for (int m = 0; m < NF; m++) acc += es[m]*vbase[(long)m*DIM + t];
        g_ao[(long)bn*DIM + t] = acc * inv;
        __syncthreads();
    }
}
__global__ __launch_bounds__(256) void xc_kernel(const float* __restrict__ x,
                                                 const float* __restrict__ gamma) {
    float g = gamma[0];
    if (g == 0.0f) return;
    for (long i = (long)blockIdx.x*256 + threadIdx.x; i < (long)BATCH*2*NF*DIM; i += (long)gridDim.x*256) {
        long b = i / (2L*NF*DIM);
        long r2 = i % (2L*NF*DIM);
        long c = r2 / DIM, l = r2 % DIM;
        float val;
        if (c < NF) { long s = (b*NF + c)*DIM + l; val = g*g_ao[s] + x[s]; }
        else        { long s = (b*NF + (c-NF))*DIM + l; val = x[s]; }
        g_xc[i] = val;
    }
}

#define TM 128
#define TN 128
#define TK 16
__device__ __forceinline__ unsigned long long splat2(float a) {
    unsigned long long r; unsigned int u = __float_as_uint(a);
    asm("mov.b64 %0, {%1, %1};" : "=l"(r) : "r"(u));
    return r;
}
__device__ __forceinline__ void fma2(unsigned long long& d, unsigned long long a, unsigned long long b) {
    asm("fma.rn.f32x2 %0, %1, %2, %0;" : "+l"(d) : "l"(a), "l"(b));
}
__device__ __forceinline__ float2 unpack2(unsigned long long v) {
    unsigned int lo, hi;
    asm("mov.b64 {%0, %1}, %2;" : "=r"(lo), "=r"(hi) : "l"(v));
    return make_float2(__uint_as_float(lo), __uint_as_float(hi));
}
template<int EPI>
__device__ __forceinline__ void sgemm_body(const float* __restrict__ A,
                                           const float* __restrict__ Bp,
                                           const float* __restrict__ bias,
                                           float* __restrict__ C, int N, int K) {
    __shared__ float As[TK][TM];
    __shared__ float Bs[TK][TN];
    int tid = threadIdx.x;
    int tx = tid & 15, ty = tid >> 4;
    int rowBase = blockIdx.y * TM;
    int colBase = blockIdx.x * TN;
    int ar = tid >> 1, ac = (tid & 1) << 3;
    int bk = tid >> 4, bn = (tid & 15) << 3;
    unsigned long long acc2[8][4];
    #pragma unroll
    for (int i = 0; i < 8; i++)
        #pragma unroll
        for (int j = 0; j < 4; j++) acc2[i][j] = 0ull;
    for (int k0 = 0; k0 < K; k0 += TK) {
        float4 a0 = *reinterpret_cast<const float4*>(&A[(long)(rowBase + ar)*K + k0 + ac]);
        float4 a1 = *reinterpret_cast<const float4*>(&A[(long)(rowBase + ar)*K + k0 + ac + 4]);
        float4 b0 = *reinterpret_cast<const float4*>(&Bp[(long)(k0 + bk)*N + colBase + bn]);
        float4 b1 = *reinterpret_cast<const float4*>(&Bp[(long)(k0 + bk)*N + colBase + bn + 4]);
        As[ac+0][ar] = a0.x; As[ac+1][ar] = a0.y; As[ac+2][ar] = a0.z; As[ac+3][ar] = a0.w;
        As[ac+4][ar] = a1.x; As[ac+5][ar] = a1.y; As[ac+6][ar] = a1.z; As[ac+7][ar] = a1.w;
        *reinterpret_cast<float4*>(&Bs[bk][bn])     = b0;
        *reinterpret_cast<float4*>(&Bs[bk][bn + 4]) = b1;
        __syncthreads();
        #pragma unroll
        for (int kk = 0; kk < TK; kk++) {
            float4 af0 = *reinterpret_cast<const float4*>(&As[kk][ty << 3]);
            float4 af1 = *reinterpret_cast<const float4*>(&As[kk][(ty << 3) + 4]);
            const unsigned long long* bpp = reinterpret_cast<const unsigned long long*>(&Bs[kk][tx << 3]);
            unsigned long long bb0 = bpp[0], bb1 = bpp[1], bb2 = bpp[2], bb3 = bpp[3];
            float av[8] = {af0.x, af0.y, af0.z, af0.w, af1.x, af1.y, af1.z, af1.w};
            #pragma unroll
            for (int i = 0; i < 8; i++) {
                unsigned long long aa = splat2(av[i]);
                fma2(acc2[i][0], aa, bb0); fma2(acc2[i][1], aa, bb1);
                fma2(acc2[i][2], aa, bb2); fma2(acc2[i][3], aa, bb3);
            }
        }
        __syncthreads();
    }
    #pragma unroll
    for (int i = 0; i < 8; i++) {
        int row = rowBase + (ty << 3) + i;
        float bv = (EPI == 1 || EPI == 3) ? bias[row] : 0.0f;
        float v[8];
        #pragma unroll
        for (int j = 0; j < 4; j++) {
            float2 p = unpack2(acc2[i][j]);
            v[2*j] = p.x + bv; v[2*j+1] = p.y + bv;
        }
        #pragma unroll
        for (int j = 0; j < 8; j++) {
            if (EPI == 1) v[j] = 1.0f/(1.0f + expf(-v[j]));
            if (EPI == 2 || EPI == 3) v[j] = (v[j] >= 0.f) ? v[j] : NEG*v[j];
        }
        *reinterpret_cast<float4*>(&C[(long)row*N + colBase + (tx << 3)])     = make_float4(v[0],v[1],v[2],v[3]);
        *reinterpret_cast<float4*>(&C[(long)row*N + colBase + (tx << 3) + 4]) = make_float4(v[4],v[5],v[6],v[7]);
    }
}
__global__ __launch_bounds__(256, 2) void simtA(const float* __restrict__ gamma,
                                                const float* __restrict__ fc_w,
                                                const float* __restrict__ fc_b) {
    if (gamma[0] == 0.0f) return;
    sgemm_body<1>(fc_w, g_xc + (long)blockIdx.z*2*NF*DIM, fc_b,
                  g_D + (long)blockIdx.z*DIM*DIM, DIM, 2*NF);
}
template<int EPI>
__global__ __launch_bounds__(256, 2) void simtG(const float* __restrict__ gamma,
                                                const float* __restrict__ Ag,
                                                const float* __restrict__ Bg,
                                                const float* __restrict__ bias,
                                                float* __restrict__ Cg,
                                                int N, int K, long sA, long sB, long sC) {
    if (gamma[0] == 0.0f) return;
    sgemm_body<EPI>(Ag + (long)blockIdx.z*sA, Bg + (long)blockIdx.z*sB, bias,
                    Cg + (long)blockIdx.z*sC, N, K);
}

// ================= launch ====================================================
extern "C" void kernel_launch(void* const* d_in, const int* in_sizes, int n_in,
                              void* d_out, int out_size) {
    const float *x = 0, *qkv_w = 0, *qkv_b = 0, *gamma = 0, *fc_w = 0, *fc_b = 0, *dw_w = 0, *dw_b = 0;
    for (int i = 0; i < n_in; i++) {
        switch (in_sizes[i]) {
            case BATCH*NF*DIM: x     = (const float*)d_in[i]; break;
            case 3*DIM*DIM:    qkv_w = (const float*)d_in[i]; break;
            case 3*DIM:        qkv_b = (const float*)d_in[i]; break;
            case 1:            gamma = (const float*)d_in[i]; break;
            case DIM*2*NF:     fc_w  = (const float*)d_in[i]; break;
            case DIM:          fc_b  = (const float*)d_in[i]; break;
            case NF*NF:        dw_w  = (const float*)d_in[i]; break;
            case NF:           dw_b  = (const float*)d_in[i]; break;
        }
    }
    float* out = (float*)d_out;

    const int DSMEM = ST * STAGE_BYTES;   // 61440
    cudaFuncSetAttribute(tgA, cudaFuncAttributeMaxDynamicSharedMemorySize, DSMEM);
    cudaFuncSetAttribute(tgB, cudaFuncAttributeMaxDynamicSharedMemorySize, DSMEM);
    cudaFuncSetAttribute(tgC, cudaFuncAttributeMaxDynamicSharedMemorySize, DSMEM);

    float *pD, *pY, *pDWhi, *pDWlo;
    cudaGetSymbolAddress((void**)&pD, g_D);
    cudaGetSymbolAddress((void**)&pY, g_Y);
    cudaGetSymbolAddress((void**)&pDWhi, g_dw_hi);
    cudaGetSymbolAddress((void**)&pDWlo, g_dw_lo);

    // ---- gamma == 0 tensor path (device-guarded) ----
    conv_wsum  <<<(DIM*NF)/256, 256>>>(fc_w, gamma);                               // 1
    conv_x     <<<dim3(NF/32, DIM/32, BATCH), dim3(32, 8)>>>(x, gamma);            // 2
    conv_split4<<<(NF*NF)/1024, 256>>>(dw_w, gamma,
                   (__nv_bfloat16*)pDWhi, (__nv_bfloat16*)pDWlo);                  // 3
    tgA<<<dim3(2, 2, BATCH), 256, DSMEM>>>(gamma, fc_b);                           // 4
    tgB<<<dim3(8, 2, BATCH), 256, DSMEM>>>(gamma);                                 // 5
    tgC<<<dim3(2, 8, BATCH), 256, DSMEM>>>(gamma, dw_b, out);                      // 6 (ncu -s 5)

    // ---- gamma != 0 fallback (device-guarded) ----
    qkv_kernel <<<1184, 256>>>(x, qkv_w, qkv_b, gamma);
    attn_kernel<<<1184, 256>>>(gamma);
    xc_kernel  <<<1024, 256>>>(x, gamma);
    simtA<<<dim3(DIM/TN, DIM/TM, BATCH), 256>>>(gamma, fc_w, fc_b);
    simtG<2><<<dim3(DIM/TN, NF/TM, BATCH), 256>>>(gamma, x, pD, nullptr, pY,
        DIM, DIM, (long)NF*DIM, (long)DIM*DIM, (long)NF*DIM);
    simtG<3><<<dim3(DIM/TN, NF/TM, BATCH), 256>>>(gamma, dw_w, pY, dw_b, out,
        DIM, NF, 0L, (long)NF*DIM, (long)NF*DIM);
}

// round 7
// speedup vs baseline: 3.0103x; 1.2310x over previous
#include <cuda_runtime.h>
#include <cuda_bf16.h>
#include <math.h>
#include <stdint.h>

#define BATCH 64
#define NF    1024
#define DIM   256
#define NEG   0.2f

// ================= device scratch (no allocs allowed) ========================
// gamma != 0 fallback path (fp32)
__device__ __align__(16) float g_q [BATCH*NF*DIM];
__device__ __align__(16) float g_k [BATCH*NF*DIM];
__device__ __align__(16) float g_v [BATCH*NF*DIM];
__device__ __align__(16) float g_ao[BATCH*NF*DIM];
__device__ __align__(16) float g_xc[BATCH*2*NF*DIM];
__device__ __align__(16) float g_D [BATCH*DIM*DIM];
__device__ __align__(16) float g_Y [BATCH*NF*DIM];
// gamma == 0 tensor path (bf16 hi/lo splits)
__device__ __align__(16) __nv_bfloat16 g_ws_hi[DIM*NF],        g_ws_lo[DIM*NF];
__device__ __align__(16) __nv_bfloat16 g_x_hi [BATCH*NF*DIM],  g_x_lo [BATCH*NF*DIM];
__device__ __align__(16) __nv_bfloat16 g_xT_hi[BATCH*DIM*NF],  g_xT_lo[BATCH*DIM*NF];
__device__ __align__(16) __nv_bfloat16 g_dw_hi[NF*NF],         g_dw_lo[NF*NF];
__device__ __align__(16) __nv_bfloat16 g_DT_hi[BATCH*DIM*DIM], g_DT_lo[BATCH*DIM*DIM];
__device__ __align__(16) __nv_bfloat16 g_YT_hi[BATCH*DIM*NF],  g_YT_lo[BATCH*DIM*NF];

// ================= PTX helpers (family-safe: sm_80-era only) =================
__device__ __forceinline__ uint32_t s2u(const void* p) {
    uint32_t a;
    asm("{ .reg .u64 t; cvta.to.shared.u64 t, %1; cvt.u32.u64 %0, t; }" : "=r"(a) : "l"(p));
    return a;
}
__device__ __forceinline__ void cp16(uint32_t dst, const void* src) {
    asm volatile("cp.async.ca.shared.global [%0], [%1], 16;" :: "r"(dst), "l"(src));
}
#define CP_COMMIT() asm volatile("cp.async.commit_group;" ::: "memory")
#define CP_WAIT1()  asm volatile("cp.async.wait_group 1;"  ::: "memory")
#define CP_WAIT0()  asm volatile("cp.async.wait_group 0;"  ::: "memory")

__device__ __forceinline__ void ldm_x4(uint32_t& r0, uint32_t& r1, uint32_t& r2, uint32_t& r3,
                                       uint32_t addr) {
    asm volatile("ldmatrix.sync.aligned.m8n8.x4.shared.b16 {%0,%1,%2,%3}, [%4];"
                 : "=r"(r0), "=r"(r1), "=r"(r2), "=r"(r3) : "r"(addr));
}
__device__ __forceinline__ void mma_bf16(float* c, const uint32_t* a, const uint32_t* b) {
    asm volatile("mma.sync.aligned.m16n8k16.row.col.f32.bf16.bf16.f32 "
                 "{%0,%1,%2,%3}, {%4,%5,%6,%7}, {%8,%9}, {%0,%1,%2,%3};"
                 : "+f"(c[0]), "+f"(c[1]), "+f"(c[2]), "+f"(c[3])
                 : "r"(a[0]), "r"(a[1]), "r"(a[2]), "r"(a[3]), "r"(b[0]), "r"(b[1]));
}
__device__ __forceinline__ uint32_t pack_bf16(__nv_bfloat16 a, __nv_bfloat16 b) {
    return (uint32_t)__bfloat16_as_ushort(a) | ((uint32_t)__bfloat16_as_ushort(b) << 16);
}

// ================= fused-split HMMA GEMM =====================================
// C[M,N] = leaky/sigmoid( Ahi@Bhi^T + Ahi@Blo^T + Alo@Bhi^T )  (all K-major)
// One k-loop; all 3 split terms issue from the SAME smem tiles into the SAME
// fp32 accumulators -> 12 ldm_x4 per 48 MMAs per warp per k16 (1.0 wf/MMA).
// CTA tile 128x128, K-chunk 32, 8 warps (4x2), warp tile 32x64.
// smem row pitch 40 bf16 (80B) -> conflict-free ldmatrix, no swizzle.
// EPI 1: sigmoid(acc + bias[col]) -> bf16 hi/lo row-major out
// EPI 2: leaky(acc)               -> bf16 hi/lo row-major out
// EPI 3: leaky(acc + bias[row])   -> fp32 row-major out
#define BK     32
#define PITCH  40
#define TILE_B 10240          // one 128x32 bf16 tile at pitch 40
#define STAGE_F (4*TILE_B)    // Ahi | Alo | Bhi | Blo

template<int EPI>
__device__ void tgemm_body(const __nv_bfloat16* __restrict__ Ahi,
                           const __nv_bfloat16* __restrict__ Alo,
                           const __nv_bfloat16* __restrict__ Bhi,
                           const __nv_bfloat16* __restrict__ Blo,
                           int K, const float* __restrict__ bias,
                           __nv_bfloat16* __restrict__ outHi,
                           __nv_bfloat16* __restrict__ outLo,
                           float* __restrict__ outF, int ldOut) {
    extern __shared__ char smc[];
    uint32_t sbase = s2u(smc);
    int tid = threadIdx.x, lane = tid & 31, wid = tid >> 5;
    int mBase = blockIdx.y * 128, nBase = blockIdx.x * 128;
    int wRow = (wid >> 1) * 32, wCol = (wid & 1) * 64;

    int total = K / BK;

    auto load_stage = [&](int s, int kk) {
        int k0 = kk * BK;
        uint32_t st = sbase + s * STAGE_F;
        const __nv_bfloat16* srcs[4] = {Ahi, Alo, Bhi, Blo};
        #pragma unroll
        for (int t = 0; t < 4; t++) {
            const __nv_bfloat16* S = srcs[t];
            int rb = (t < 2) ? mBase : nBase;
            uint32_t toff = st + t * TILE_B;
            #pragma unroll
            for (int q = 0; q < 2; q++) {
                int ch = tid * 2 + q;             // 0..511
                int row = ch >> 2, c16 = ch & 3;
                uint32_t d = (uint32_t)(row * PITCH + c16 * 8) * 2;
                cp16(toff + d, S + (size_t)(rb + row) * K + k0 + c16 * 8);
            }
        }
        CP_COMMIT();
    };

    load_stage(0, 0);
    load_stage(1, 1);

    float acc[2][8][4];
    #pragma unroll
    for (int i = 0; i < 2; i++)
        #pragma unroll
        for (int j = 0; j < 8; j++)
            #pragma unroll
            for (int q = 0; q < 4; q++) acc[i][j][q] = 0.0f;

    for (int kk = 0; kk < total; kk++) {
        if (kk + 1 < total) { CP_WAIT1(); } else { CP_WAIT0(); }
        __syncthreads();
        uint32_t st = sbase + (uint32_t)(kk & 1) * STAGE_F;
        uint32_t aTh = st, aTl = st + TILE_B, bTh = st + 2*TILE_B, bTl = st + 3*TILE_B;
        #pragma unroll
        for (int kf = 0; kf < 2; kf++) {
            uint32_t ah[2][4], al[2][4];
            #pragma unroll
            for (int i = 0; i < 2; i++) {
                int r = wRow + i * 16 + (lane & 15);
                int c = kf * 16 + ((lane & 16) ? 8 : 0);
                uint32_t d = (uint32_t)(r * PITCH + c) * 2;
                ldm_x4(ah[i][0], ah[i][1], ah[i][2], ah[i][3], aTh + d);
                ldm_x4(al[i][0], al[i][1], al[i][2], al[i][3], aTl + d);
            }
            uint32_t bh[8][2], bl[8][2];
            #pragma unroll
            for (int nf2 = 0; nf2 < 4; nf2++) {
                int n = wCol + nf2 * 16 + (lane & 7) + ((lane & 16) ? 8 : 0);
                int c = kf * 16 + ((lane & 8) ? 8 : 0);
                uint32_t d = (uint32_t)(n * PITCH + c) * 2;
                uint32_t r0, r1, r2, r3;
                ldm_x4(r0, r1, r2, r3, bTh + d);
                bh[nf2*2][0] = r0; bh[nf2*2][1] = r1;
                bh[nf2*2+1][0] = r2; bh[nf2*2+1][1] = r3;
                ldm_x4(r0, r1, r2, r3, bTl + d);
                bl[nf2*2][0] = r0; bl[nf2*2][1] = r1;
                bl[nf2*2+1][0] = r2; bl[nf2*2+1][1] = r3;
            }
            #pragma unroll
            for (int i = 0; i < 2; i++)
                #pragma unroll
                for (int j = 0; j < 8; j++) {
                    mma_bf16(acc[i][j], ah[i], bh[j]);
                    mma_bf16(acc[i][j], ah[i], bl[j]);
                    mma_bf16(acc[i][j], al[i], bh[j]);
                }
        }
        __syncthreads();
        if (kk + 2 < total) load_stage(kk & 1, kk + 2);
    }

    // ---- epilogue (no transpose needed anywhere) ----
    int r0 = mBase + wRow + (lane >> 2);
    int c0 = nBase + wCol + (lane & 3) * 2;
    #pragma unroll
    for (int i = 0; i < 2; i++) {
        #pragma unroll
        for (int h = 0; h < 2; h++) {
            int row = r0 + i * 16 + h * 8;
            float rbv = (EPI == 3) ? bias[row] : 0.0f;
            #pragma unroll
            for (int j = 0; j < 8; j++) {
                float v0 = acc[i][j][h*2+0];
                float v1 = acc[i][j][h*2+1];
                int col = c0 + j * 8;
                if (EPI == 1) {
                    v0 += bias[col]; v1 += bias[col + 1];
                    v0 = 1.0f / (1.0f + expf(-v0));
                    v1 = 1.0f / (1.0f + expf(-v1));
                } else if (EPI == 2) {
                    v0 = (v0 >= 0.f) ? v0 : NEG * v0;
                    v1 = (v1 >= 0.f) ? v1 : NEG * v1;
                } else {
                    v0 += rbv; v1 += rbv;
                    v0 = (v0 >= 0.f) ? v0 : NEG * v0;
                    v1 = (v1 >= 0.f) ? v1 : NEG * v1;
                }
                if (EPI == 3) {
                    *reinterpret_cast<float2*>(outF + (size_t)row * ldOut + col) =
                        make_float2(v0, v1);
                } else {
                    __nv_bfloat16 h0 = __float2bfloat16_rn(v0);
                    __nv_bfloat16 h1 = __float2bfloat16_rn(v1);
                    __nv_bfloat16 l0 = __float2bfloat16_rn(v0 - __bfloat162float(h0));
                    __nv_bfloat16 l1 = __float2bfloat16_rn(v1 - __bfloat162float(h1));
                    size_t off = (size_t)row * ldOut + col;
                    *reinterpret_cast<uint32_t*>(outHi + off) = pack_bf16(h0, h1);
                    *reinterpret_cast<uint32_t*>(outLo + off) = pack_bf16(l0, l1);
                }
            }
        }
    }
}

// DT[l,o] = sigmoid( xT_b[l,:] . Wsum[o,:] + fc_b[o] )      M=256,N=256,K=1024
__global__ __launch_bounds__(256, 2)
void tgA(const float* __restrict__ gamma, const float* __restrict__ fc_b) {
    if (gamma[0] != 0.0f) return;
    size_t b = blockIdx.z;
    tgemm_body<1>(g_xT_hi + b * DIM * NF, g_xT_lo + b * DIM * NF,
                  g_ws_hi, g_ws_lo, NF, fc_b,
                  g_DT_hi + b * DIM * DIM, g_DT_lo + b * DIM * DIM, nullptr, DIM);
}
// YT[l,n] = leaky( DT_b[l,:] . x_b[n,:] )                    M=256,N=1024,K=256
__global__ __launch_bounds__(256, 2)
void tgB(const float* __restrict__ gamma) {
    if (gamma[0] != 0.0f) return;
    size_t b = blockIdx.z;
    tgemm_body<2>(g_DT_hi + b * DIM * DIM, g_DT_lo + b * DIM * DIM,
                  g_x_hi + b * NF * DIM, g_x_lo + b * NF * DIM, DIM, nullptr,
                  g_YT_hi + b * DIM * NF, g_YT_lo + b * DIM * NF, nullptr, NF);
}
// out[o,l] = leaky( dw[o,:] . YT_b[l,:] + dw_b[o] )          M=1024,N=256,K=1024
__global__ __launch_bounds__(256, 2)
void tgC(const float* __restrict__ gamma, const float* __restrict__ dw_b,
         float* __restrict__ out) {
    if (gamma[0] != 0.0f) return;
    size_t b = blockIdx.z;
    tgemm_body<3>(g_dw_hi, g_dw_lo,
                  g_YT_hi + b * DIM * NF, g_YT_lo + b * DIM * NF, NF, dw_b,
                  nullptr, nullptr, out + b * NF * DIM, DIM);
}

// ================= conversion kernels (gamma == 0) ===========================
__global__ void conv_wsum(const float* __restrict__ fc_w, const float* __restrict__ gamma) {
    if (gamma[0] != 0.0f) return;
    int i = blockIdx.x * 256 + threadIdx.x;           // < DIM*NF
    int o = i >> 10, c = i & 1023;
    float w = fc_w[(size_t)o * 2048 + c] + fc_w[(size_t)o * 2048 + 1024 + c];
    __nv_bfloat16 h = __float2bfloat16_rn(w);
    g_ws_hi[i] = h;
    g_ws_lo[i] = __float2bfloat16_rn(w - __bfloat162float(h));
}
// x -> straight split (g_x) AND transposed split (g_xT) in one pass
__global__ void conv_x(const float* __restrict__ x, const float* __restrict__ gamma) {
    if (gamma[0] != 0.0f) return;
    __shared__ float t[32][33];
    int n0 = blockIdx.x * 32, d0 = blockIdx.y * 32, b = blockIdx.z;
    int tx = threadIdx.x, ty = threadIdx.y;
    const float* xb = x + (size_t)b * NF * DIM;
    #pragma unroll
    for (int i = 0; i < 4; i++) {
        int n = n0 + ty + 8 * i;
        float v = xb[(size_t)n * DIM + d0 + tx];
        t[ty + 8 * i][tx] = v;
        __nv_bfloat16 h = __float2bfloat16_rn(v);
        size_t o = (size_t)b * NF * DIM + (size_t)n * DIM + d0 + tx;
        g_x_hi[o] = h;
        g_x_lo[o] = __float2bfloat16_rn(v - __bfloat162float(h));
    }
    __syncthreads();
    #pragma unroll
    for (int i = 0; i < 4; i++) {
        int d = d0 + ty + 8 * i, n = n0 + tx;
        float v = t[tx][ty + 8 * i];
        __nv_bfloat16 h = __float2bfloat16_rn(v);
        size_t o = (size_t)b * DIM * NF + (size_t)d * NF + n;
        g_xT_hi[o] = h;
        g_xT_lo[o] = __float2bfloat16_rn(v - __bfloat162float(h));
    }
}
__global__ void conv_split4(const float* __restrict__ src, const float* __restrict__ gamma,
                            __nv_bfloat16* __restrict__ hi, __nv_bfloat16* __restrict__ lo) {
    if (gamma[0] != 0.0f) return;
    size_t i = ((size_t)blockIdx.x * 256 + threadIdx.x) * 4;
    float4 v = *reinterpret_cast<const float4*>(src + i);
    __nv_bfloat16 h0 = __float2bfloat16_rn(v.x), h1 = __float2bfloat16_rn(v.y);
    __nv_bfloat16 h2 = __float2bfloat16_rn(v.z), h3 = __float2bfloat16_rn(v.w);
    uint2 ho, lw;
    ho.x = pack_bf16(h0, h1); ho.y = pack_bf16(h2, h3);
    lw.x = pack_bf16(__float2bfloat16_rn(v.x - __bfloat162float(h0)),
                     __float2bfloat16_rn(v.y - __bfloat162float(h1)));
    lw.y = pack_bf16(__float2bfloat16_rn(v.z - __bfloat162float(h2)),
                     __float2bfloat16_rn(v.w - __bfloat162float(h3)));
    *reinterpret_cast<uint2*>(hi + i) = ho;
    *reinterpret_cast<uint2*>(lo + i) = lw;
}

// ================= gamma != 0 fallback (SIMT f32x2 path) =====================
__global__ __launch_bounds__(256) void qkv_kernel(const float* __restrict__ x,
                                                  const float* __restrict__ w,
                                                  const float* __restrict__ bias,
                                                  const float* __restrict__ gamma) {
    if (gamma[0] == 0.0f) return;
    __shared__ float xs[DIM];
    for (int row = blockIdx.x; row < BATCH*NF; row += gridDim.x) {
        xs[threadIdx.x] = x[(long)row*DIM + threadIdx.x];
        __syncthreads();
        for (int e = threadIdx.x; e < 3*DIM; e += 256) {
            float acc = bias[e];
            const float* wr = w + (long)e*DIM;
            #pragma unroll 4
            for (int d = 0; d < DIM; d++) acc += xs[d]*wr[d];
            float* dst = (e < DIM) ? g_q : (e < 2*DIM ? g_k : g_v);
            dst[(long)row*DIM + (e & (DIM-1))] = acc;
        }
        __syncthreads();
    }
}
__global__ __launch_bounds__(256) void attn_kernel(const float* __restrict__ gamma) {
    if (gamma[0] == 0.0f) return;
    __shared__ float qs[DIM];
    __shared__ float es[NF];
    __shared__ float red[256];
    int t = threadIdx.x;
    for (int bn = blockIdx.x; bn < BATCH*NF; bn += gridDim.x) {
        int bb = bn / NF;
        qs[t] = g_q[(long)bn*DIM + t];
        __syncthreads();
        const float* kbase = g_k + (long)bb*NF*DIM;
        for (int m = t; m < NF; m += 256) {
            float acc = 0.0f;
            const float* kr = kbase + (long)m*DIM;
            #pragma unroll 4
            for (int d = 0; d < DIM; d++) acc += qs[d]*kr[d];
            es[m] = acc;
        }
        __syncthreads();
        float mx = -INFINITY;
        for (int m = t; m < NF; m += 256) mx = fmaxf(mx, es[m]);
        red[t] = mx; __syncthreads();
        for (int s = 128; s > 0; s >>= 1) { if (t < s) red[t] = fmaxf(red[t], red[t+s]); __syncthreads(); }
        mx = red[0]; __syncthreads();
        float sm = 0.0f;
        for (int m = t; m < NF; m += 256) { float e = expf(es[m]-mx); es[m] = e; sm += e; }
        red[t] = sm; __syncthreads();
        for (int s = 128; s > 0; s >>= 1) { if (t < s) red[t] += red[t+s]; __syncthreads(); }
        float inv = 1.0f / red[0];
        __syncthreads();
        const float* vbase = g_v + (long)bb*NF*DIM;
        float acc = 0.0f;
        for (int m = 0; m < NF; m++) acc += es[m]*vbase[(long)m*DIM + t];
        g_ao[(long)bn*DIM + t] = acc * inv;
        __syncthreads();
    }
}
__global__ __launch_bounds__(256) void xc_kernel(const float* __restrict__ x,
                                                 const float* __restrict__ gamma) {
    float g = gamma[0];
    if (g == 0.0f) return;
    for (long i = (long)blockIdx.x*256 + threadIdx.x; i < (long)BATCH*2*NF*DIM; i += (long)gridDim.x*256) {
        long b = i / (2L*NF*DIM);
        long r2 = i % (2L*NF*DIM);
        long c = r2 / DIM, l = r2 % DIM;
        float val;
        if (c < NF) { long s = (b*NF + c)*DIM + l; val = g*g_ao[s] + x[s]; }
        else        { long s = (b*NF + (c-NF))*DIM + l; val = x[s]; }
        g_xc[i] = val;
    }
}

#define TM 128
#define TN 128
#define TK 16
__device__ __forceinline__ unsigned long long splat2(float a) {
    unsigned long long r; unsigned int u = __float_as_uint(a);
    asm("mov.b64 %0, {%1, %1};" : "=l"(r) : "r"(u));
    return r;
}
__device__ __forceinline__ void fma2(unsigned long long& d, unsigned long long a, unsigned long long b) {
    asm("fma.rn.f32x2 %0, %1, %2, %0;" : "+l"(d) : "l"(a), "l"(b));
}
__device__ __forceinline__ float2 unpack2(unsigned long long v) {
    unsigned int lo, hi;
    asm("mov.b64 {%0, %1}, %2;" : "=r"(lo), "=r"(hi) : "l"(v));
    return make_float2(__uint_as_float(lo), __uint_as_float(hi));
}
template<int EPI>
__device__ __forceinline__ void sgemm_body(const float* __restrict__ A,
                                           const float* __restrict__ Bp,
                                           const float* __restrict__ bias,
                                           float* __restrict__ C, int N, int K) {
    __shared__ float As[TK][TM];
    __shared__ float Bs[TK][TN];
    int tid = threadIdx.x;
    int tx = tid & 15, ty = tid >> 4;
    int rowBase = blockIdx.y * TM;
    int colBase = blockIdx.x * TN;
    int ar = tid >> 1, ac = (tid & 1) << 3;
    int bk = tid >> 4, bn = (tid & 15) << 3;
    unsigned long long acc2[8][4];
    #pragma unroll
    for (int i = 0; i < 8; i++)
        #pragma unroll
        for (int j = 0; j < 4; j++) acc2[i][j] = 0ull;
    for (int k0 = 0; k0 < K; k0 += TK) {
        float4 a0 = *reinterpret_cast<const float4*>(&A[(long)(rowBase + ar)*K + k0 + ac]);
        float4 a1 = *reinterpret_cast<const float4*>(&A[(long)(rowBase + ar)*K + k0 + ac + 4]);
        float4 b0 = *reinterpret_cast<const float4*>(&Bp[(long)(k0 + bk)*N + colBase + bn]);
        float4 b1 = *reinterpret_cast<const float4*>(&Bp[(long)(k0 + bk)*N + colBase + bn + 4]);
        As[ac+0][ar] = a0.x; As[ac+1][ar] = a0.y; As[ac+2][ar] = a0.z; As[ac+3][ar] = a0.w;
        As[ac+4][ar] = a1.x; As[ac+5][ar] = a1.y; As[ac+6][ar] = a1.z; As[ac+7][ar] = a1.w;
        *reinterpret_cast<float4*>(&Bs[bk][bn])     = b0;
        *reinterpret_cast<float4*>(&Bs[bk][bn + 4]) = b1;
        __syncthreads();
        #pragma unroll
        for (int kk = 0; kk < TK; kk++) {
            float4 af0 = *reinterpret_cast<const float4*>(&As[kk][ty << 3]);
            float4 af1 = *reinterpret_cast<const float4*>(&As[kk][(ty << 3) + 4]);
            const unsigned long long* bpp = reinterpret_cast<const unsigned long long*>(&Bs[kk][tx << 3]);
            unsigned long long bb0 = bpp[0], bb1 = bpp[1], bb2 = bpp[2], bb3 = bpp[3];
            float av[8] = {af0.x, af0.y, af0.z, af0.w, af1.x, af1.y, af1.z, af1.w};
            #pragma unroll
            for (int i = 0; i < 8; i++) {
                unsigned long long aa = splat2(av[i]);
                fma2(acc2[i][0], aa, bb0); fma2(acc2[i][1], aa, bb1);
                fma2(acc2[i][2], aa, bb2); fma2(acc2[i][3], aa, bb3);
            }
        }
        __syncthreads();
    }
    #pragma unroll
    for (int i = 0; i < 8; i++) {
        int row = rowBase + (ty << 3) + i;
        float bv = (EPI == 1 || EPI == 3) ? bias[row] : 0.0f;
        float v[8];
        #pragma unroll
        for (int j = 0; j < 4; j++) {
            float2 p = unpack2(acc2[i][j]);
            v[2*j] = p.x + bv; v[2*j+1] = p.y + bv;
        }
        #pragma unroll
        for (int j = 0; j < 8; j++) {
            if (EPI == 1) v[j] = 1.0f/(1.0f + expf(-v[j]));
            if (EPI == 2 || EPI == 3) v[j] = (v[j] >= 0.f) ? v[j] : NEG*v[j];
        }
        *reinterpret_cast<float4*>(&C[(long)row*N + colBase + (tx << 3)])     = make_float4(v[0],v[1],v[2],v[3]);
        *reinterpret_cast<float4*>(&C[(long)row*N + colBase + (tx << 3) + 4]) = make_float4(v[4],v[5],v[6],v[7]);
    }
}
__global__ __launch_bounds__(256, 2) void simtA(const float* __restrict__ gamma,
                                                const float* __restrict__ fc_w,
                                                const float* __restrict__ fc_b) {
    if (gamma[0] == 0.0f) return;
    sgemm_body<1>(fc_w, g_xc + (long)blockIdx.z*2*NF*DIM, fc_b,
                  g_D + (long)blockIdx.z*DIM*DIM, DIM, 2*NF);
}
template<int EPI>
__global__ __launch_bounds__(256, 2) void simtG(const float* __restrict__ gamma,
                                                const float* __restrict__ Ag,
                                                const float* __restrict__ Bg,
                                                const float* __restrict__ bias,
                                                float* __restrict__ Cg,
                                                int N, int K, long sA, long sB, long sC) {
    if (gamma[0] == 0.0f) return;
    sgemm_body<EPI>(Ag + (long)blockIdx.z*sA, Bg + (long)blockIdx.z*sB, bias,
                    Cg + (long)blockIdx.z*sC, N, K);
}

// ================= launch ====================================================
extern "C" void kernel_launch(void* const* d_in, const int* in_sizes, int n_in,
                              void* d_out, int out_size) {
    const float *x = 0, *qkv_w = 0, *qkv_b = 0, *gamma = 0, *fc_w = 0, *fc_b = 0, *dw_w = 0, *dw_b = 0;
    for (int i = 0; i < n_in; i++) {
        switch (in_sizes[i]) {
            case BATCH*NF*DIM: x     = (const float*)d_in[i]; break;
            case 3*DIM*DIM:    qkv_w = (const float*)d_in[i]; break;
            case 3*DIM:        qkv_b = (const float*)d_in[i]; break;
            case 1:            gamma = (const float*)d_in[i]; break;
            case DIM*2*NF:     fc_w  = (const float*)d_in[i]; break;
            case DIM:          fc_b  = (const float*)d_in[i]; break;
            case NF*NF:        dw_w  = (const float*)d_in[i]; break;
            case NF:           dw_b  = (const float*)d_in[i]; break;
        }
    }
    float* out = (float*)d_out;

    const int DSMEM = 2 * STAGE_F;   // 81920
    cudaFuncSetAttribute(tgA, cudaFuncAttributeMaxDynamicSharedMemorySize, DSMEM);
    cudaFuncSetAttribute(tgB, cudaFuncAttributeMaxDynamicSharedMemorySize, DSMEM);
    cudaFuncSetAttribute(tgC, cudaFuncAttributeMaxDynamicSharedMemorySize, DSMEM);

    float *pD, *pY, *pDWhi, *pDWlo;
    cudaGetSymbolAddress((void**)&pD, g_D);
    cudaGetSymbolAddress((void**)&pY, g_Y);
    cudaGetSymbolAddress((void**)&pDWhi, g_dw_hi);
    cudaGetSymbolAddress((void**)&pDWlo, g_dw_lo);

    // ---- gamma == 0 tensor path (device-guarded) ----
    conv_wsum  <<<(DIM*NF)/256, 256>>>(fc_w, gamma);                               // 1
    conv_x     <<<dim3(NF/32, DIM/32, BATCH), dim3(32, 8)>>>(x, gamma);            // 2
    conv_split4<<<(NF*NF)/1024, 256>>>(dw_w, gamma,
                   (__nv_bfloat16*)pDWhi, (__nv_bfloat16*)pDWlo);                  // 3
    tgA<<<dim3(2, 2, BATCH), 256, DSMEM>>>(gamma, fc_b);                           // 4
    tgB<<<dim3(8, 2, BATCH), 256, DSMEM>>>(gamma);                                 // 5
    tgC<<<dim3(2, 8, BATCH), 256, DSMEM>>>(gamma, dw_b, out);                      // 6 (ncu -s 5)

    // ---- gamma != 0 fallback (device-guarded) ----
    qkv_kernel <<<1184, 256>>>(x, qkv_w, qkv_b, gamma);
    attn_kernel<<<1184, 256>>>(gamma);
    xc_kernel  <<<1024, 256>>>(x, gamma);
    simtA<<<dim3(DIM/TN, DIM/TM, BATCH), 256>>>(gamma, fc_w, fc_b);
    simtG<2><<<dim3(DIM/TN, NF/TM, BATCH), 256>>>(gamma, x, pD, nullptr, pY,
        DIM, DIM, (long)NF*DIM, (long)DIM*DIM, (long)NF*DIM);
    simtG<3><<<dim3(DIM/TN, NF/TM, BATCH), 256>>>(gamma, dw_w, pY, dw_b, out,
        DIM, NF, 0L, (long)NF*DIM, (long)NF*DIM);
}